// round 1
// baseline (speedup 1.0000x reference)
#include <cuda_runtime.h>
#include <math.h>

constexpr int   NELEM  = 8192;
constexpr int   TPB    = 256;
constexpr int   JCHUNK = 1024;
constexpr float THRESH = 0.05f;
constexpr float MSEW   = 10.0f;
constexpr float LEPS   = 1e-7f;

// scratch (no allocation allowed -> device globals)
__device__ float2 g_pd[NELEM];              // (psi_i, d_i = pred_i - logit_i)
__device__ double g_sumsq;
__device__ unsigned long long g_count;
__device__ float  g_bce;

__global__ void init_kernel() {
    g_sumsq = 0.0;
    g_count = 0ull;
    g_bce   = 0.0f;
}

__global__ void prep_kernel(const float* __restrict__ pred,
                            const float* __restrict__ psi) {
    int i = blockIdx.x * blockDim.x + threadIdx.x;
    float x = pred[i];
    float y = psi[i];

    // BCE-with-logits term (numerically stable form, matches reference)
    float bce = fmaxf(x, 0.0f) - x * y + log1pf(expf(-fabsf(x)));

    // logit with clamp
    float p = fminf(fmaxf(y, LEPS), 1.0f - LEPS);
    float l = logf(p) - log1pf(-p);
    g_pd[i] = make_float2(y, x - l);

    // block-reduce bce, one atomic per block
    __shared__ float sh[TPB / 32];
    float v = bce;
    #pragma unroll
    for (int o = 16; o > 0; o >>= 1) v += __shfl_down_sync(0xffffffffu, v, o);
    if ((threadIdx.x & 31) == 0) sh[threadIdx.x >> 5] = v;
    __syncthreads();
    if (threadIdx.x < 32) {
        v = (threadIdx.x < TPB / 32) ? sh[threadIdx.x] : 0.0f;
        #pragma unroll
        for (int o = 4; o > 0; o >>= 1) v += __shfl_down_sync(0xffffffffu, v, o);
        if (threadIdx.x == 0) atomicAdd(&g_bce, v);
    }
}

__global__ void __launch_bounds__(TPB) pair_kernel() {
    __shared__ float2 sh[JCHUNK];

    int i  = blockIdx.x * blockDim.x + threadIdx.x;   // my row
    int j0 = blockIdx.y * JCHUNK;                     // my column chunk

    // cooperative chunk load (coalesced LDG.64)
    #pragma unroll
    for (int k = threadIdx.x; k < JCHUNK; k += TPB)
        sh[k] = g_pd[j0 + k];
    __syncthreads();

    float2 mi   = g_pd[i];
    float psi_i = mi.x;
    float d_i   = mi.y;

    float sumsq = 0.0f;
    int   cnt   = 0;

    #pragma unroll 8
    for (int k = 0; k < JCHUNK; ++k) {
        float2 pj  = sh[k];                 // broadcast LDS.64 (all lanes same addr)
        float dpsi = psi_i - pj.x;
        float dd   = d_i   - pj.y;
        bool  v    = fabsf(dpsi) >= THRESH; // FSETP with |abs|
        if (v) {                            // predicated FFMA / IADD
            sumsq = fmaf(dd, dd, sumsq);
            cnt++;
        }
    }

    // block reduction: float sumsq + int cnt
    __shared__ float  shs[TPB / 32];
    __shared__ int    shc[TPB / 32];
    float s = sumsq;
    int   c = cnt;
    #pragma unroll
    for (int o = 16; o > 0; o >>= 1) {
        s += __shfl_down_sync(0xffffffffu, s, o);
        c += __shfl_down_sync(0xffffffffu, c, o);
    }
    if ((threadIdx.x & 31) == 0) {
        shs[threadIdx.x >> 5] = s;
        shc[threadIdx.x >> 5] = c;
    }
    __syncthreads();
    if (threadIdx.x < 32) {
        s = (threadIdx.x < TPB / 32) ? shs[threadIdx.x] : 0.0f;
        c = (threadIdx.x < TPB / 32) ? shc[threadIdx.x] : 0;
        #pragma unroll
        for (int o = 4; o > 0; o >>= 1) {
            s += __shfl_down_sync(0xffffffffu, s, o);
            c += __shfl_down_sync(0xffffffffu, c, o);
        }
        if (threadIdx.x == 0) {
            atomicAdd(&g_sumsq, (double)s);
            atomicAdd(&g_count, (unsigned long long)(unsigned int)c);
        }
    }
}

__global__ void fin_kernel(float* __restrict__ out,
                           const int* __restrict__ flag) {
    float bce = g_bce / (float)NELEM;
    int bce_only = (flag != nullptr) ? *flag : 0;
    if (bce_only) {
        out[0] = bce;
        return;
    }
    unsigned long long c = g_count;
    float n = (float)(c ? c : 1ull);
    float mse = (float)(g_sumsq / (double)n);
    out[0] = (c > 0) ? (bce + MSEW * mse) : bce;
}

extern "C" void kernel_launch(void* const* d_in, const int* in_sizes, int n_in,
                              void* d_out, int out_size) {
    const float* pred = (const float*)d_in[0];
    const float* psi  = (const float*)d_in[1];
    const int*   flag = (n_in >= 3 && in_sizes[2] >= 1) ? (const int*)d_in[2] : nullptr;

    init_kernel<<<1, 1>>>();
    prep_kernel<<<NELEM / TPB, TPB>>>(pred, psi);
    dim3 grid(NELEM / TPB, NELEM / JCHUNK);     // 32 x 8 = 256 blocks
    pair_kernel<<<grid, TPB>>>();
    fin_kernel<<<1, 1>>>((float*)d_out, flag);
}

// round 2
// speedup vs baseline: 1.2775x; 1.2775x over previous
#include <cuda_runtime.h>
#include <math.h>

constexpr int   NELEM  = 8192;
constexpr int   TPB    = 256;
constexpr int   IPT    = 2;            // i-values per thread
constexpr int   JCHUNK = 512;          // j-tile in shared
constexpr int   GRIDX  = NELEM / (TPB * IPT);   // 16
constexpr int   GRIDY  = NELEM / JCHUNK;        // 16
constexpr int   NBLK   = GRIDX * GRIDY;         // 256
constexpr float THRESH = 0.05f;
constexpr float MSEW   = 10.0f;
constexpr float LEPS   = 1e-7f;

// per-block partial slots (written every launch -> no init kernel needed)
__device__ float        g_ps[NBLK];
__device__ int          g_pc[NBLK];
__device__ float        g_pb[NBLK];
__device__ unsigned int g_arr;   // zero at module load; self-resets each launch

__device__ __forceinline__ float2 compute_pd(float x, float y) {
    // (psi, d = pred - logit(psi));  p in [0.5-range] so 1-p is exact (Sterbenz)
    float p = fminf(fmaxf(y, LEPS), 1.0f - LEPS);
    float l = __logf(p) - __logf(1.0f - p);
    return make_float2(y, x - l);
}

__global__ void __launch_bounds__(TPB)
fused_kernel(const float* __restrict__ pred,
             const float* __restrict__ psi,
             const int*   __restrict__ flag,
             float*       __restrict__ out) {
    __shared__ float2 sh[JCHUNK];
    __shared__ float  shs[TPB / 32];
    __shared__ int    shc[TPB / 32];
    __shared__ float  shb[TPB / 32];
    __shared__ int    sh_last;

    const int tid = threadIdx.x;
    const int bx  = blockIdx.x;        // i-block
    const int by  = blockIdx.y;        // j-chunk
    const int j0  = by * JCHUNK;

    // build j tile (psi_j, d_j) in shared
    #pragma unroll
    for (int k = tid; k < JCHUNK; k += TPB) {
        int j = j0 + k;
        sh[k] = compute_pd(pred[j], psi[j]);
    }

    // my two i rows
    const int i0 = bx * (TPB * IPT) + tid;
    const int i1 = i0 + TPB;
    float x0 = pred[i0], y0 = psi[i0];
    float x1 = pred[i1], y1 = psi[i1];
    float2 pd0 = compute_pd(x0, y0);
    float2 pd1 = compute_pd(x1, y1);

    // BCE partial: only the by==0 stripe covers each i exactly once
    float bce = 0.0f;
    if (by == 0) {
        bce = (fmaxf(x0, 0.0f) - x0 * y0 + log1pf(__expf(-fabsf(x0))))
            + (fmaxf(x1, 0.0f) - x1 * y1 + log1pf(__expf(-fabsf(x1))));
    }
    __syncthreads();

    float s0 = 0.0f, s1 = 0.0f;
    int   c0 = 0,    c1 = 0;
    #pragma unroll 8
    for (int k = 0; k < JCHUNK; ++k) {
        float2 pj = sh[k];                      // broadcast LDS.64
        float dp0 = pd0.x - pj.x, dd0 = pd0.y - pj.y;
        float dp1 = pd1.x - pj.x, dd1 = pd1.y - pj.y;
        if (fabsf(dp0) >= THRESH) { s0 = fmaf(dd0, dd0, s0); c0++; }
        if (fabsf(dp1) >= THRESH) { s1 = fmaf(dd1, dd1, s1); c1++; }
    }
    float s = s0 + s1;
    int   c = c0 + c1;

    // block reduction (s, c, bce)
    #pragma unroll
    for (int o = 16; o > 0; o >>= 1) {
        s   += __shfl_down_sync(0xffffffffu, s,   o);
        c   += __shfl_down_sync(0xffffffffu, c,   o);
        bce += __shfl_down_sync(0xffffffffu, bce, o);
    }
    if ((tid & 31) == 0) {
        shs[tid >> 5] = s; shc[tid >> 5] = c; shb[tid >> 5] = bce;
    }
    __syncthreads();
    if (tid < 32) {
        s   = (tid < TPB / 32) ? shs[tid] : 0.0f;
        c   = (tid < TPB / 32) ? shc[tid] : 0;
        bce = (tid < TPB / 32) ? shb[tid] : 0.0f;
        #pragma unroll
        for (int o = 4; o > 0; o >>= 1) {
            s   += __shfl_down_sync(0xffffffffu, s,   o);
            c   += __shfl_down_sync(0xffffffffu, c,   o);
            bce += __shfl_down_sync(0xffffffffu, bce, o);
        }
        if (tid == 0) {
            int slot = by * GRIDX + bx;
            g_ps[slot] = s;
            g_pc[slot] = c;
            g_pb[slot] = bce;
            __threadfence();
            unsigned t = atomicAdd(&g_arr, 1u);
            sh_last = (t == (unsigned)(NBLK - 1));
            if (sh_last) __threadfence();
        }
    }
    __syncthreads();

    if (sh_last) {
        // last block reduces all 256 partial slots (deterministic order)
        float fs = __ldcg(&g_ps[tid]);
        int   fc = __ldcg(&g_pc[tid]);
        float fb = __ldcg(&g_pb[tid]);
        #pragma unroll
        for (int o = 16; o > 0; o >>= 1) {
            fs += __shfl_down_sync(0xffffffffu, fs, o);
            fc += __shfl_down_sync(0xffffffffu, fc, o);
            fb += __shfl_down_sync(0xffffffffu, fb, o);
        }
        __syncthreads();   // protect re-use of shs/shc/shb
        if ((tid & 31) == 0) {
            shs[tid >> 5] = fs; shc[tid >> 5] = fc; shb[tid >> 5] = fb;
        }
        __syncthreads();
        if (tid == 0) {
            fs = 0.0f; fc = 0; fb = 0.0f;
            #pragma unroll
            for (int w = 0; w < TPB / 32; ++w) {
                fs += shs[w]; fc += shc[w]; fb += shb[w];
            }
            float bce_mean = fb / (float)NELEM;
            int bce_only = (flag != nullptr) ? *flag : 0;
            float result;
            if (bce_only) {
                result = bce_mean;
            } else {
                float n   = (float)(fc > 0 ? fc : 1);
                float mse = fs / n;
                result = (fc > 0) ? (bce_mean + MSEW * mse) : bce_mean;
            }
            out[0] = result;
            g_arr  = 0u;   // self-reset for next graph replay
        }
    }
}

extern "C" void kernel_launch(void* const* d_in, const int* in_sizes, int n_in,
                              void* d_out, int out_size) {
    const float* pred = (const float*)d_in[0];
    const float* psi  = (const float*)d_in[1];
    const int*   flag = (n_in >= 3 && in_sizes[2] >= 1) ? (const int*)d_in[2] : nullptr;

    dim3 grid(GRIDX, GRIDY);   // 16 x 16 = 256 blocks
    fused_kernel<<<grid, TPB>>>(pred, psi, flag, (float*)d_out);
}